// round 11
// baseline (speedup 1.0000x reference)
#include <cuda_runtime.h>
#include <cuda_bf16.h>
#include <math.h>

#define KS    11
#define HALO  5
#define IMG   512
#define TW    128          // tile width (outputs)
#define TH    32           // tile height (outputs)
#define NPAIR 70           // column pairs loaded: cols [x0-6, x0+134)
#define PSTR  33           // row slots per pair (32 + 1 pad) -> conflict-free
#define NROWS (TH + KS - 1)   // 42
#define NTHR  128

typedef unsigned long long ull;

__device__ float2 g_w2[KS];

// Pre-kernel: normalized 1D Gaussian, stored as (w, w) pairs for f32x2 FMA.
__global__ void gb_weights_kernel(const float* __restrict__ sigma) {
    if (threadIdx.x == 0) {
        float s = fabsf(sigma[0]) + 1e-6f;
        float inv2s2 = 1.0f / (2.0f * s * s);
        float w[KS];
        float sum = 0.0f;
        #pragma unroll
        for (int i = 0; i < KS; i++) {
            float r = (float)i - (float)(KS - 1) * 0.5f;
            w[i] = expf(-(r * r) * inv2s2);
            sum += w[i];
        }
        float inv = 1.0f / sum;
        #pragma unroll
        for (int i = 0; i < KS; i++) g_w2[i] = make_float2(w[i] * inv, w[i] * inv);
    }
}

__device__ __forceinline__ int reflect_idx(int i) {
    i = (i < 0) ? -i : i;
    return (i > IMG - 1) ? 2 * (IMG - 1) - i : i;
}

// d = a * b + c, element-wise on packed f32x2
__device__ __forceinline__ ull fma2(ull a, ull b, ull c) {
    ull d;
    asm("fma.rn.f32x2 %0, %1, %2, %3;" : "=l"(d) : "l"(a), "l"(b), "l"(c));
    return d;
}
__device__ __forceinline__ ull pack2(float lo, float hi) {
    ull d;
    asm("mov.b64 %0, {%1, %2};" : "=l"(d) : "f"(lo), "f"(hi));
    return d;
}
// (hi(a), lo(b)) : the odd-aligned pair between two even-aligned pairs
__device__ __forceinline__ ull oddpair(ull a, ull b) {
    ull d;
    asm("{\n\t"
        ".reg .f32 alo, ahi, blo, bhi;\n\t"
        "mov.b64 {alo, ahi}, %1;\n\t"
        "mov.b64 {blo, bhi}, %2;\n\t"
        "mov.b64 %0, {ahi, blo};\n\t"
        "}" : "=l"(d) : "l"(a), "l"(b));
    return d;
}

__global__ void __launch_bounds__(NTHR, 8)
gb_blur_kernel(const float* __restrict__ x, float* __restrict__ out) {
    __shared__ ull tmp2[NPAIR * PSTR];   // [pair][row-slot], 18.5 KB
    __shared__ int yoff[NROWS];          // reflected row byte-offsets

    const int tid   = threadIdx.x;
    const int plane = blockIdx.z;
    const int x0    = blockIdx.x * TW;
    const int y0    = blockIdx.y * TH;

    const float* __restrict__ base = x + (size_t)plane * (IMG * IMG);

    // Precompute 42 reflected row offsets (bytes) once per block.
    if (tid < NROWS) {
        int y = reflect_idx(y0 - HALO + tid);
        yoff[tid] = y * (IMG * 4);
    }

    // Packed weights: 11 x u64.
    ull w2[KS];
    #pragma unroll
    for (int k = 0; k < KS; k++) w2[k] = __ldg((const ull*)&g_w2[k]);

    __syncthreads();

    // ---------------- P1: vertical pass (packed column pairs) ----------------
    // Thread t owns column pair (x0-6+2t, x0-6+2t+1). Interior: one LDG.64 per
    // row. Boundary pairs (reflected, non-contiguous): two scalar LDGs + pack.
    // 11 FFMA2 per row -> STS.64 into pair-major tmp2[t][r].
    if (tid < NPAIR) {
        const int cx = x0 - 6 + 2 * tid;
        ull* __restrict__ trow = tmp2 + tid * PSTR;

        if (cx >= 0 && cx <= IMG - 2) {
            const char* __restrict__ p = (const char*)(base + cx);
            ull win[KS];
            #pragma unroll
            for (int i = 0; i < KS - 1; i++)
                win[i] = __ldg((const ull*)(p + yoff[i]));
            #pragma unroll
            for (int r = 0; r < TH; r++) {
                win[(r + KS - 1) % KS] = __ldg((const ull*)(p + yoff[r + KS - 1]));
                ull acc = 0;
                #pragma unroll
                for (int k = 0; k < KS; k++)
                    acc = fma2(win[(r + k) % KS], w2[k], acc);
                trow[r] = acc;
            }
        } else {
            const char* __restrict__ p0 = (const char*)(base + reflect_idx(cx));
            const char* __restrict__ p1 = (const char*)(base + reflect_idx(cx + 1));
            ull win[KS];
            #pragma unroll
            for (int i = 0; i < KS - 1; i++)
                win[i] = pack2(__ldg((const float*)(p0 + yoff[i])),
                               __ldg((const float*)(p1 + yoff[i])));
            #pragma unroll
            for (int r = 0; r < TH; r++) {
                win[(r + KS - 1) % KS] =
                    pack2(__ldg((const float*)(p0 + yoff[r + KS - 1])),
                          __ldg((const float*)(p1 + yoff[r + KS - 1])));
                ull acc = 0;
                #pragma unroll
                for (int k = 0; k < KS; k++)
                    acc = fma2(win[(r + k) % KS], w2[k], acc);
                trow[r] = acc;
            }
        }
    }
    __syncthreads();

    // ---------------- P2: horizontal pass (packed x-pairs) ----------------
    // Warp cs (0..3) owns output columns [32cs, 32cs+32). Lane -> (r_loc =
    // lane>>3, xo = lane&7), x = 32cs + 4xo. Per row-group: 8 even pairs via
    // LDS.64 (bank-bijective), 7 odd pairs via register movs, 22 FFMA2 -> 4
    // outputs -> one 16B STG (coalesced: 8 lanes per 128B line).
    const int cs    = tid >> 5;
    const int lane  = tid & 31;
    const int r_loc = lane >> 3;
    const int xo    = lane & 7;
    const int xbase = cs * 32 + xo * 4;

    const ull* __restrict__ tp = tmp2 + (xbase >> 1) * PSTR;  // e[j] at tp[j*PSTR + row]
    float* __restrict__ ocol =
        out + (size_t)plane * (IMG * IMG) + (size_t)y0 * IMG + x0 + xbase;

    #pragma unroll
    for (int rg = 0; rg < 8; rg++) {
        const int row = rg * 4 + r_loc;
        const ull* __restrict__ t = tp + row;

        ull e0 = t[0 * PSTR], e1 = t[1 * PSTR], e2 = t[2 * PSTR], e3 = t[3 * PSTR];
        ull e4 = t[4 * PSTR], e5 = t[5 * PSTR], e6 = t[6 * PSTR], e7 = t[7 * PSTR];

        ull o0 = oddpair(e0, e1), o1 = oddpair(e1, e2), o2 = oddpair(e2, e3);
        ull o3 = oddpair(e3, e4), o4 = oddpair(e4, e5), o5 = oddpair(e5, e6);
        ull o6 = oddpair(e6, e7);

        // outputs (x, x+1)
        ull a0 = 0;
        a0 = fma2(o0, w2[0], a0);  a0 = fma2(e1, w2[1], a0);
        a0 = fma2(o1, w2[2], a0);  a0 = fma2(e2, w2[3], a0);
        a0 = fma2(o2, w2[4], a0);  a0 = fma2(e3, w2[5], a0);
        a0 = fma2(o3, w2[6], a0);  a0 = fma2(e4, w2[7], a0);
        a0 = fma2(o4, w2[8], a0);  a0 = fma2(e5, w2[9], a0);
        a0 = fma2(o5, w2[10], a0);
        // outputs (x+2, x+3)
        ull a1 = 0;
        a1 = fma2(o1, w2[0], a1);  a1 = fma2(e2, w2[1], a1);
        a1 = fma2(o2, w2[2], a1);  a1 = fma2(e3, w2[3], a1);
        a1 = fma2(o3, w2[4], a1);  a1 = fma2(e4, w2[5], a1);
        a1 = fma2(o4, w2[6], a1);  a1 = fma2(e5, w2[7], a1);
        a1 = fma2(o5, w2[8], a1);  a1 = fma2(e6, w2[9], a1);
        a1 = fma2(o6, w2[10], a1);

        ulonglong2 st;
        st.x = a0; st.y = a1;
        *reinterpret_cast<ulonglong2*>(ocol + (size_t)row * IMG) = st;
    }
}

extern "C" void kernel_launch(void* const* d_in, const int* in_sizes, int n_in,
                              void* d_out, int out_size) {
    const float* x     = (const float*)d_in[0];   // (16, 64, 512, 512) fp32
    const float* sigma = (const float*)d_in[1];   // (1,) fp32
    float* out = (float*)d_out;

    gb_weights_kernel<<<1, 32>>>(sigma);

    dim3 grid(IMG / TW, IMG / TH, 16 * 64);       // (4, 16, 1024)
    gb_blur_kernel<<<grid, NTHR>>>(x, out);
}

// round 12
// speedup vs baseline: 1.4569x; 1.4569x over previous
#include <cuda_runtime.h>
#include <cuda_bf16.h>
#include <math.h>

#define KS    11
#define HALO  5
#define IMG   512
#define TW    128   // tile width (outputs)
#define TH    32    // tile height (outputs)
#define TSTR  139   // tmp row stride: 139 mod 32 = 11, gcd(11,32)=1 -> conflict-free
#define PSTR  65    // patch row stride: 65 mod 32 = 1 -> conflict-free
#define NTHR  256

__device__ float g_w[KS];

// Pre-kernel: normalized 1D Gaussian weights from sigma (separable 2D kernel).
__global__ void gb_weights_kernel(const float* __restrict__ sigma) {
    if (threadIdx.x == 0) {
        float s = fabsf(sigma[0]) + 1e-6f;
        float inv2s2 = 1.0f / (2.0f * s * s);
        float w[KS];
        float sum = 0.0f;
        #pragma unroll
        for (int i = 0; i < KS; i++) {
            float r = (float)i - (float)(KS - 1) * 0.5f;
            w[i] = expf(-(r * r) * inv2s2);
            sum += w[i];
        }
        float inv = 1.0f / sum;
        #pragma unroll
        for (int i = 0; i < KS; i++) g_w[i] = w[i] * inv;
    }
}

__device__ __forceinline__ int reflect_lo(int i) { return i < 0 ? -i : i; }
__device__ __forceinline__ int reflect_hi(int i) { return i > (IMG - 1) ? 2 * (IMG - 1) - i : i; }

__global__ void __launch_bounds__(NTHR)
gb_blur_kernel(const float* __restrict__ x, float* __restrict__ out) {
    __shared__ float tmp[TH * TSTR];      // vertical-blur intermediate (32 x 139) 17.8 KB
    __shared__ float patch[TH * PSTR];    // transpose buffer (32 x 65)          8.3 KB

    const int tid   = threadIdx.x;
    const int plane = blockIdx.z;
    const int x0    = blockIdx.x * TW;
    const int y0    = blockIdx.y * TH;

    const float* __restrict__ base = x + (size_t)plane * (IMG * IMG);

    float w[KS];
    #pragma unroll
    for (int k = 0; k < KS; k++) w[k] = __ldg(&g_w[k]);

    // ---------------- P1: vertical pass, global -> tmp (identical to R2) -----
    // One thread per halo column (138). Warp lanes read consecutive x
    // (coalesced). Sliding 11-register window down the column.
    if (tid < TW + 2 * HALO) {
        int cx = x0 - HALO + tid;
        cx = reflect_hi(reflect_lo(cx));
        const float* __restrict__ col = base + cx;

        float win[KS];
        #pragma unroll
        for (int i = 0; i < KS - 1; i++) {
            int y = reflect_lo(y0 - HALO + i);       // only low reflect possible
            win[i] = __ldg(col + y * IMG);
        }

        #pragma unroll
        for (int r = 0; r < TH; r++) {
            int y = reflect_hi(y0 + HALO + r);       // only high reflect possible
            win[(r + KS - 1) % KS] = __ldg(col + y * IMG);

            float acc = 0.0f;
            #pragma unroll
            for (int k = 0; k < KS; k++)
                acc = fmaf(win[(r + k) % KS], w[k], acc);

            tmp[r * TSTR + tid] = acc;
        }
    }
    __syncthreads();

    // ---------------- P2: horizontal pass in two 64-col halves ---------------
    // Compute: thread (row = tid&31, seg = tid>>5) -> 8 outputs per half,
    //   cols h*64 + seg*8 .. +7. tmp reads: bank = row*11 + C (bijective).
    //   Results go to patch[row][seg*8+j]: bank = row + C (bijective).
    // Store: thread (prow = tid>>3, c = tid&7 + 8*ii): 4 scalar patch reads
    //   (banks r' + 4c + i bijective per warp) -> one float4 STG with lanes
    //   along x: 4 cache lines per warp-inst (minimal).
    const int row  = tid & 31;
    const int seg  = tid >> 5;            // 0..7
    const int prow = tid >> 3;            // 0..31
    const int pc   = (tid & 7) * 4;       // 0,4,...,28

    float* __restrict__ oplane = out + (size_t)plane * (IMG * IMG);

    #pragma unroll
    for (int h = 0; h < 2; h++) {
        const int hbase = h * 64;

        // -- compute half into patch --
        {
            const float* __restrict__ trow = tmp + row * TSTR + hbase + seg * 8;
            float* __restrict__ prow_out = patch + row * PSTR + seg * 8;

            float win[KS];
            #pragma unroll
            for (int i = 0; i < KS - 1; i++) win[i] = trow[i];

            #pragma unroll
            for (int j = 0; j < 8; j++) {
                win[(j + KS - 1) % KS] = trow[(KS - 1) + j];
                float acc = 0.0f;
                #pragma unroll
                for (int k = 0; k < KS; k++)
                    acc = fmaf(win[(j + k) % KS], w[k], acc);
                prow_out[j] = acc;
            }
        }
        __syncthreads();

        // -- coalesced store of the half --
        #pragma unroll
        for (int ii = 0; ii < 2; ii++) {
            const int col = pc + ii * 32;                 // 0..60, mult of 4
            const float* __restrict__ pr = patch + prow * PSTR + col;
            float4 v = make_float4(pr[0], pr[1], pr[2], pr[3]);
            float4* __restrict__ o = reinterpret_cast<float4*>(
                oplane + (size_t)(y0 + prow) * IMG + x0 + hbase + col);
            *o = v;
        }
        __syncthreads();   // patch reused by next half
    }
}

extern "C" void kernel_launch(void* const* d_in, const int* in_sizes, int n_in,
                              void* d_out, int out_size) {
    const float* x     = (const float*)d_in[0];   // (16, 64, 512, 512) fp32
    const float* sigma = (const float*)d_in[1];   // (1,) fp32
    float* out = (float*)d_out;

    gb_weights_kernel<<<1, 32>>>(sigma);

    dim3 grid(IMG / TW, IMG / TH, 16 * 64);       // (4, 16, 1024)
    gb_blur_kernel<<<grid, NTHR>>>(x, out);
}

// round 16
// speedup vs baseline: 1.9590x; 1.3446x over previous
#include <cuda_runtime.h>
#include <cuda_bf16.h>
#include <math.h>

#define KS    11
#define HALO  5
#define IMG   512
#define TW    128   // tile width (outputs)
#define TH    32    // tile height (outputs)
#define TSTR  139   // tmp row stride: 139 mod 32 = 11, gcd(11,32)=1 -> conflict-free
#define PSTR  129   // patch row stride: 129 mod 32 = 1 -> conflict-free
#define NTHR  256

__device__ float g_w[KS];

// Pre-kernel: normalized 1D Gaussian weights from sigma (separable kernel).
__global__ void gb_weights_kernel(const float* __restrict__ sigma) {
    if (threadIdx.x == 0) {
        float s = fabsf(sigma[0]) + 1e-6f;
        float inv2s2 = 1.0f / (2.0f * s * s);
        float w[KS];
        float sum = 0.0f;
        #pragma unroll
        for (int i = 0; i < KS; i++) {
            float r = (float)i - (float)(KS - 1) * 0.5f;
            w[i] = expf(-(r * r) * inv2s2);
            sum += w[i];
        }
        float inv = 1.0f / sum;
        #pragma unroll
        for (int i = 0; i < KS; i++) g_w[i] = w[i] * inv;
    }
}

__device__ __forceinline__ int reflect_lo(int i) { return i < 0 ? -i : i; }
__device__ __forceinline__ int reflect_hi(int i) { return i > (IMG - 1) ? 2 * (IMG - 1) - i : i; }

__global__ void __launch_bounds__(NTHR, 6)
gb_blur_kernel(const float* __restrict__ x, float* __restrict__ out) {
    __shared__ float tmp[TH * TSTR];      // vertical-blur intermediate  17.8 KB
    __shared__ float patch[TH * PSTR];    // transposed output staging   16.5 KB

    const int tid   = threadIdx.x;
    const int plane = blockIdx.z;
    const int x0    = blockIdx.x * TW;
    const int y0    = blockIdx.y * TH;

    const float* __restrict__ base = x + (size_t)plane * (IMG * IMG);

    float w[KS];
    #pragma unroll
    for (int k = 0; k < KS; k++) w[k] = __ldg(&g_w[k]);

    // ---------------- P1: vertical pass, global -> tmp -----------------------
    // One thread per halo column (138, coalesced lanes). Rows processed in 4
    // chunks of 8: each chunk batch-loads 8 INDEPENDENT rows (MLP ~8), then
    // computes 8 outputs from win[10] + nxt[8] with static indexing.
    if (tid < TW + 2 * HALO) {
        int cx = reflect_hi(reflect_lo(x0 - HALO + tid));
        const float* __restrict__ col = base + cx;

        float win[KS - 1];                       // rows r .. r+9 (relative)
        #pragma unroll
        for (int i = 0; i < KS - 1; i++) {
            int y = reflect_lo(y0 - HALO + i);   // only low reflect possible
            win[i] = __ldg(col + y * IMG);
        }

        #pragma unroll
        for (int c = 0; c < 4; c++) {
            float nxt[8];
            #pragma unroll
            for (int i = 0; i < 8; i++) {
                int y = reflect_hi(y0 + HALO + 8 * c + i);   // only high reflect
                nxt[i] = __ldg(col + y * IMG);
            }
            #pragma unroll
            for (int j = 0; j < 8; j++) {
                float acc = 0.0f;
                #pragma unroll
                for (int k = 0; k + j <= 9; k++)             // taps 0..9-j
                    acc = fmaf(win[j + k], w[k], acc);
                #pragma unroll
                for (int i = 0; i <= j; i++)                 // taps 10-j..10
                    acc = fmaf(nxt[i], w[10 - j + i], acc);
                tmp[(8 * c + j) * TSTR + tid] = acc;
            }
            // shift window: new rows r+8 .. r+17
            win[0] = win[8]; win[1] = win[9];
            #pragma unroll
            for (int i = 0; i < 8; i++) win[2 + i] = nxt[i];
        }
    }
    __syncthreads();

    // ---------------- P2: horizontal pass, tmp -> patch ----------------------
    // Warp seg owns cols [16*seg, 16*seg+16), lane = row. tmp reads: bank =
    // 11*row + C (bijective). patch writes: bank = row + C (bijective).
    {
        const int row = tid & 31;
        const int seg = tid >> 5;                 // 0..7
        const float* __restrict__ trow = tmp + row * TSTR + seg * 16;
        float* __restrict__ pr = patch + row * PSTR + seg * 16;

        float win2[KS];
        #pragma unroll
        for (int i = 0; i < KS - 1; i++) win2[i] = trow[i];

        #pragma unroll
        for (int j = 0; j < 16; j++) {
            win2[(j + KS - 1) % KS] = trow[(KS - 1) + j];
            float acc = 0.0f;
            #pragma unroll
            for (int k = 0; k < KS; k++)
                acc = fmaf(win2[(j + k) % KS], w[k], acc);
            pr[j] = acc;
        }
    }
    __syncthreads();

    // ---------------- P3: coalesced store, patch -> global -------------------
    // lane -> (prow = tid>>3, pc = (tid&7)*4): patch reads bank-bijective,
    // float4 STG with lanes along x: 4 cache lines per warp-inst (minimal).
    {
        const int prow = tid >> 3;                // 0..31
        const int pc   = (tid & 7) * 4;           // 0,4,...,28
        float* __restrict__ orow =
            out + (size_t)plane * (IMG * IMG) + (size_t)(y0 + prow) * IMG + x0;

        #pragma unroll
        for (int ii = 0; ii < 4; ii++) {
            const int col = pc + 32 * ii;         // 0..124, multiple of 4
            const float* __restrict__ pr = patch + prow * PSTR + col;
            float4 v = make_float4(pr[0], pr[1], pr[2], pr[3]);
            *reinterpret_cast<float4*>(orow + col) = v;
        }
    }
}

extern "C" void kernel_launch(void* const* d_in, const int* in_sizes, int n_in,
                              void* d_out, int out_size) {
    const float* x     = (const float*)d_in[0];   // (16, 64, 512, 512) fp32
    const float* sigma = (const float*)d_in[1];   // (1,) fp32
    float* out = (float*)d_out;

    gb_weights_kernel<<<1, 32>>>(sigma);

    dim3 grid(IMG / TW, IMG / TH, 16 * 64);       // (4, 16, 1024)
    gb_blur_kernel<<<grid, NTHR>>>(x, out);
}